// round 3
// baseline (speedup 1.0000x reference)
#include <cuda_runtime.h>
#include <cuda_bf16.h>
#include <math.h>

#define EPSF 1e-7f
#define MAX_NORM (1.0f - 1e-5f)
#define MAXN 131072
#define MAXE 2097152
#define D 64

// ---------------- device scratch (no allocations allowed) ----------------
__device__ __align__(16) float g_wh[D * D];               // expmap0(weight)
__device__ __align__(16) float g_bh[D];                   // expmap0(bias)
__device__ float g_bh2;                                   // ||b_h||^2
__device__ __align__(16) float g_hbuf[(size_t)MAXN * D];  // transformed node features
__device__ int g_cnt[MAXN];                               // in-degree counts
__device__ int g_off[MAXN + 1];                           // CSR offsets
__device__ int g_cur[MAXN];                               // placement cursors
__device__ int g_srcs[MAXE];                              // CSR src list (grouped by dst)

// ---------------- kernel: zero counters ----------------
__global__ void zero_cnt_kernel(int N) {
    int i = blockIdx.x * 256 + threadIdx.x;
    if (i < N) g_cnt[i] = 0;
}

// ---------------- kernel: parameter transform (tiny) ----------------
__global__ void prep_kernel(const float* __restrict__ weight,
                            const float* __restrict__ bias) {
    int t = threadIdx.x; // 64 threads, thread t owns weight row t
    float row[D];
    float n2 = 0.0f;
#pragma unroll
    for (int j = 0; j < D; j++) {
        float v = weight[t * D + j];
        row[j] = v;
        n2 += v * v;
    }
    float n = fmaxf(sqrtf(n2), EPSF);
    float s = tanhf(n) / n;
#pragma unroll
    for (int j = 0; j < D; j++) g_wh[t * D + j] = s * row[j];

    // bias expmap0 (cooperative norm over 64 threads)
    __shared__ float sh[D];
    float b = bias[t];
    sh[t] = b * b;
    __syncthreads();
    if (t == 0) {
        float s2 = 0.0f;
#pragma unroll
        for (int i = 0; i < D; i++) s2 += sh[i];
        sh[0] = s2;
    }
    __syncthreads();
    float bn2 = sh[0];
    float bn = fmaxf(sqrtf(bn2), EPSF);
    float bs = tanhf(bn) / bn;
    g_bh[t] = bs * b;
    if (t == 0) g_bh2 = bs * bs * bn2; // exact ||b_h||^2
}

// ---------------- kernel: node transform (warp per node) ----------------
__global__ __launch_bounds__(256) void transform_kernel(const float* __restrict__ x, int N) {
    __shared__ float2 Ws[D * 32]; // Ws[i*32+t] = (w_h[i][2t], w_h[i][2t+1])
    __shared__ float Bs[D];
    __shared__ float b2s;
    int tid = threadIdx.x;
    const float2* whv = (const float2*)g_wh;
    for (int i = tid; i < D * 32; i += 256) Ws[i] = whv[i];
    if (tid < D) Bs[tid] = g_bh[tid];
    if (tid == 0) b2s = g_bh2;
    __syncthreads();

    int warp = tid >> 5, lane = tid & 31;
    int node = blockIdx.x * 8 + warp;
    if (node >= N) return;

    float2 v = ((const float2*)x)[(size_t)node * 32 + lane];
    float xn2 = v.x * v.x + v.y * v.y;
#pragma unroll
    for (int o = 16; o; o >>= 1) xn2 += __shfl_xor_sync(0xffffffffu, xn2, o);
    float xn = fmaxf(sqrtf(xn2), EPSF);

    float m0 = 0.0f, m1 = 0.0f;
#pragma unroll
    for (int i = 0; i < D; i++) {
        float sel = (i & 1) ? v.y : v.x;
        float xi = __shfl_sync(0xffffffffu, sel, i >> 1);
        float2 w = Ws[i * 32 + lane];
        m0 = fmaf(xi, w.x, m0);
        m1 = fmaf(xi, w.y, m1);
    }
    float mn2 = m0 * m0 + m1 * m1;
#pragma unroll
    for (int o = 16; o; o >>= 1) mn2 += __shfl_xor_sync(0xffffffffu, mn2, o);
    float Mxn = fmaxf(sqrtf(mn2), EPSF);

    float xc = fminf(xn, 1.0f - 1e-7f);
    float art = 0.5f * log1pf(2.0f * xc / (1.0f - xc));
    float sc = tanhf(Mxn / xn * art) / Mxn;
    float h0 = sc * m0, h1 = sc * m1;

    float2 bb = ((const float2*)Bs)[lane];
    float xy = h0 * bb.x + h1 * bb.y;
    float xx = h0 * h0 + h1 * h1;
#pragma unroll
    for (int o = 16; o; o >>= 1) {
        xy += __shfl_xor_sync(0xffffffffu, xy, o);
        xx += __shfl_xor_sync(0xffffffffu, xx, o);
    }
    float y2 = b2s;
    float ca = 1.0f + 2.0f * xy + y2;
    float cb = 1.0f - xx;
    float den = fmaxf(1.0f + 2.0f * xy + xx * y2, EPSF);
    float inv = 1.0f / den;
    float2 hout = make_float2((ca * h0 + cb * bb.x) * inv,
                              (ca * h1 + cb * bb.y) * inv);
    ((float2*)g_hbuf)[(size_t)node * 32 + lane] = hout;
}

// ---------------- kernel: degree count (edge_index stored as int32) ----------------
__global__ __launch_bounds__(256) void count_kernel(const int* __restrict__ ei, int E) {
    int e = blockIdx.x * 256 + threadIdx.x;
    if (e >= E) return;
    int dst = __ldg(&ei[(size_t)E + e]);
    atomicAdd(&g_cnt[dst], 1);
}

// ---------------- kernel: single-block chunked exclusive scan ----------------
__global__ __launch_bounds__(1024) void scan_kernel(int N) {
    __shared__ int warp_sums[32];
    __shared__ int carry_s;
    int tid = threadIdx.x;
    int lane = tid & 31, wid = tid >> 5;
    if (tid == 0) carry_s = 0;
    __syncthreads();
    for (int base = 0; base < N; base += 1024) {
        int i = base + tid;
        int v = (i < N) ? g_cnt[i] : 0;
        int s = v;
#pragma unroll
        for (int o = 1; o < 32; o <<= 1) {
            int t = __shfl_up_sync(0xffffffffu, s, o);
            if (lane >= o) s += t;
        }
        if (lane == 31) warp_sums[wid] = s;
        __syncthreads();
        if (wid == 0) {
            int ws = warp_sums[lane];
#pragma unroll
            for (int o = 1; o < 32; o <<= 1) {
                int t = __shfl_up_sync(0xffffffffu, ws, o);
                if (lane >= o) ws += t;
            }
            warp_sums[lane] = ws;
        }
        __syncthreads();
        int warp_off = (wid == 0) ? 0 : warp_sums[wid - 1];
        int carry_now = carry_s;
        int excl = carry_now + warp_off + s - v;
        if (i < N) { g_off[i] = excl; g_cur[i] = excl; }
        __syncthreads();
        if (tid == 1023) carry_s = carry_now + warp_sums[31];
        __syncthreads();
    }
    if (tid == 0) g_off[N] = carry_s;
}

// ---------------- kernel: CSR placement ----------------
__global__ __launch_bounds__(256) void place_kernel(const int* __restrict__ ei, int E) {
    int e = blockIdx.x * 256 + threadIdx.x;
    if (e >= E) return;
    int src = __ldg(&ei[e]);
    int dst = __ldg(&ei[(size_t)E + e]);
    int slot = atomicAdd(&g_cur[dst], 1);
    g_srcs[slot] = src;
}

// ---------------- kernel: gather + mean + project ----------------
__global__ __launch_bounds__(256) void gather_kernel(float* __restrict__ out, int N) {
    int gw = (blockIdx.x * 256 + threadIdx.x) >> 5; // global warp = node
    int lane = threadIdx.x & 31;
    if (gw >= N) return;
    int beg = g_off[gw], end = g_off[gw + 1];
    const float2* hb = (const float2*)g_hbuf;
    float ax = 0.0f, ay = 0.0f;
    int j = beg;
    for (; j + 1 < end; j += 2) {
        int s0 = g_srcs[j];
        int s1 = g_srcs[j + 1];
        float2 a = hb[(size_t)s0 * 32 + lane];
        float2 b = hb[(size_t)s1 * 32 + lane];
        ax += a.x + b.x;
        ay += a.y + b.y;
    }
    if (j < end) {
        int s0 = g_srcs[j];
        float2 a = hb[(size_t)s0 * 32 + lane];
        ax += a.x;
        ay += a.y;
    }
    float dg = (float)(end - beg);
    float inv = 1.0f / fmaxf(dg, 1.0f);
    ax *= inv; ay *= inv;
    float n2 = ax * ax + ay * ay;
#pragma unroll
    for (int o = 16; o; o >>= 1) n2 += __shfl_xor_sync(0xffffffffu, n2, o);
    float nn = fmaxf(sqrtf(n2), EPSF);
    float sc = (nn > MAX_NORM) ? (MAX_NORM / nn) : 1.0f;
    ((float2*)out)[(size_t)gw * 32 + lane] = make_float2(ax * sc, ay * sc);
}

// ---------------- launch ----------------
extern "C" void kernel_launch(void* const* d_in, const int* in_sizes, int n_in,
                              void* d_out, int out_size) {
    const float* x      = (const float*)d_in[0];
    const float* weight = (const float*)d_in[1];
    const float* bias   = (const float*)d_in[2];
    const int*   ei     = (const int*)d_in[3];   // edge_index stored as int32
    float* out = (float*)d_out;

    int N = in_sizes[0] / D;
    int E = in_sizes[3] / 2;

    zero_cnt_kernel<<<(N + 255) / 256, 256>>>(N);
    prep_kernel<<<1, 64>>>(weight, bias);
    transform_kernel<<<(N + 7) / 8, 256>>>(x, N);
    count_kernel<<<(E + 255) / 256, 256>>>(ei, E);
    scan_kernel<<<1, 1024>>>(N);
    place_kernel<<<(E + 255) / 256, 256>>>(ei, E);
    gather_kernel<<<(N + 7) / 8, 256>>>(out, N);
}

// round 4
// speedup vs baseline: 1.4076x; 1.4076x over previous
#include <cuda_runtime.h>
#include <cuda_bf16.h>
#include <math.h>

#define EPSF 1e-7f
#define MAX_NORM (1.0f - 1e-5f)
#define MAXN 131072
#define MAXE 2097152
#define D 64

// ---------------- device scratch (no allocations allowed) ----------------
__device__ __align__(16) float g_wh[D * D];               // expmap0(weight)
__device__ __align__(16) float g_bh[D];                   // expmap0(bias)
__device__ float g_bh2;                                   // ||b_h||^2
__device__ __align__(16) float g_hbuf[(size_t)MAXN * D];  // transformed node features
__device__ int g_cnt[MAXN];                               // in-degree counts
__device__ int g_off[MAXN + 1];                           // CSR offsets
__device__ int g_cur[MAXN];                               // placement cursors
__device__ int g_srcs[MAXE];                              // CSR src list (grouped by dst)
__device__ int g_bsum[1024];                              // per-chunk sums
__device__ int g_bsumx[1024];                             // exclusive-scanned chunk sums

// ============ K0: zero counters + parameter transform (fused) ============
__global__ __launch_bounds__(256) void zero_prep_kernel(const float* __restrict__ weight,
                                                        const float* __restrict__ bias,
                                                        int N, int zblocks) {
    int b = blockIdx.x;
    if (b < zblocks) {
        int i = b * 256 + threadIdx.x;
        if (i < N) g_cnt[i] = 0;
        return;
    }
    // prep block: 64 active threads
    int t = threadIdx.x;
    __shared__ float sh[D];
    if (t < D) {
        float row[D];
        float n2 = 0.0f;
#pragma unroll
        for (int j = 0; j < D; j++) {
            float v = weight[t * D + j];
            row[j] = v;
            n2 += v * v;
        }
        float n = fmaxf(sqrtf(n2), EPSF);
        float s = tanhf(n) / n;
#pragma unroll
        for (int j = 0; j < D; j++) g_wh[t * D + j] = s * row[j];
        float bb = bias[t];
        sh[t] = bb * bb;
    }
    __syncthreads();
    if (t == 0) {
        float s2 = 0.0f;
#pragma unroll
        for (int i = 0; i < D; i++) s2 += sh[i];
        sh[0] = s2;
    }
    __syncthreads();
    if (t < D) {
        float bn2 = sh[0];
        float bn = fmaxf(sqrtf(bn2), EPSF);
        float bs = tanhf(bn) / bn;
        g_bh[t] = bs * bias[t];
        if (t == 0) g_bh2 = bs * bs * bn2;
    }
}

// ============ K1: node transform + degree count (fused, role by blockIdx) ============
__global__ __launch_bounds__(256) void transform_count_kernel(const float* __restrict__ x,
                                                              const int* __restrict__ ei,
                                                              int N, int E, int tblocks) {
    int b = blockIdx.x;
    if (b >= tblocks) {
        // ---- count role ----
        int e = (b - tblocks) * 256 + threadIdx.x;
        if (e < E) {
            int dst = __ldg(&ei[(size_t)E + e]);
            atomicAdd(&g_cnt[dst], 1);
        }
        return;
    }
    // ---- transform role: warp per node ----
    __shared__ float2 Ws[D * 32];
    __shared__ float Bs[D];
    __shared__ float b2s;
    int tid = threadIdx.x;
    const float2* whv = (const float2*)g_wh;
    for (int i = tid; i < D * 32; i += 256) Ws[i] = whv[i];
    if (tid < D) Bs[tid] = g_bh[tid];
    if (tid == 0) b2s = g_bh2;
    __syncthreads();

    int warp = tid >> 5, lane = tid & 31;
    int node = b * 8 + warp;
    if (node >= N) return;

    float2 v = ((const float2*)x)[(size_t)node * 32 + lane];
    float xn2 = v.x * v.x + v.y * v.y;
#pragma unroll
    for (int o = 16; o; o >>= 1) xn2 += __shfl_xor_sync(0xffffffffu, xn2, o);
    float xn = fmaxf(sqrtf(xn2), EPSF);

    float m0 = 0.0f, m1 = 0.0f;
#pragma unroll
    for (int i = 0; i < D; i++) {
        float sel = (i & 1) ? v.y : v.x;
        float xi = __shfl_sync(0xffffffffu, sel, i >> 1);
        float2 w = Ws[i * 32 + lane];
        m0 = fmaf(xi, w.x, m0);
        m1 = fmaf(xi, w.y, m1);
    }
    float mn2 = m0 * m0 + m1 * m1;
#pragma unroll
    for (int o = 16; o; o >>= 1) mn2 += __shfl_xor_sync(0xffffffffu, mn2, o);
    float Mxn = fmaxf(sqrtf(mn2), EPSF);

    float xc = fminf(xn, 1.0f - 1e-7f);
    float art = 0.5f * log1pf(2.0f * xc / (1.0f - xc));
    float sc = tanhf(Mxn / xn * art) / Mxn;
    float h0 = sc * m0, h1 = sc * m1;

    float2 bb = ((const float2*)Bs)[lane];
    float xy = h0 * bb.x + h1 * bb.y;
    float xx = h0 * h0 + h1 * h1;
#pragma unroll
    for (int o = 16; o; o >>= 1) {
        xy += __shfl_xor_sync(0xffffffffu, xy, o);
        xx += __shfl_xor_sync(0xffffffffu, xx, o);
    }
    float y2 = b2s;
    float ca = 1.0f + 2.0f * xy + y2;
    float cb = 1.0f - xx;
    float den = fmaxf(1.0f + 2.0f * xy + xx * y2, EPSF);
    float inv = 1.0f / den;
    ((float2*)g_hbuf)[(size_t)node * 32 + lane] =
        make_float2((ca * h0 + cb * bb.x) * inv, (ca * h1 + cb * bb.y) * inv);
}

// ============ K2: per-chunk reduce (1024 elems/block) ============
__global__ __launch_bounds__(1024) void scan_reduce_kernel(int N) {
    int tid = threadIdx.x, lane = tid & 31, wid = tid >> 5;
    int i = blockIdx.x * 1024 + tid;
    int v = (i < N) ? g_cnt[i] : 0;
#pragma unroll
    for (int o = 16; o; o >>= 1) v += __shfl_xor_sync(0xffffffffu, v, o);
    __shared__ int ws[32];
    if (lane == 0) ws[wid] = v;
    __syncthreads();
    if (wid == 0) {
        int s = ws[lane];
#pragma unroll
        for (int o = 16; o; o >>= 1) s += __shfl_xor_sync(0xffffffffu, s, o);
        if (lane == 0) g_bsum[blockIdx.x] = s;
    }
}

// ============ K3: scan chunk sums (single block, <=1024 chunks) ============
__global__ __launch_bounds__(1024) void scan_tops_kernel(int nchunk, int N) {
    int tid = threadIdx.x, lane = tid & 31, wid = tid >> 5;
    int v = (tid < nchunk) ? g_bsum[tid] : 0;
    int s = v;
#pragma unroll
    for (int o = 1; o < 32; o <<= 1) {
        int t = __shfl_up_sync(0xffffffffu, s, o);
        if (lane >= o) s += t;
    }
    __shared__ int ws[32];
    if (lane == 31) ws[wid] = s;
    __syncthreads();
    if (wid == 0) {
        int w = ws[lane];
#pragma unroll
        for (int o = 1; o < 32; o <<= 1) {
            int t = __shfl_up_sync(0xffffffffu, w, o);
            if (lane >= o) w += t;
        }
        ws[lane] = w;
    }
    __syncthreads();
    int warp_off = (wid == 0) ? 0 : ws[wid - 1];
    g_bsumx[tid] = warp_off + s - v;
    if (tid == 0) g_off[N] = ws[31];
}

// ============ K4: block-local rescan + base, write offsets ============
__global__ __launch_bounds__(1024) void scan_write_kernel(int N) {
    int tid = threadIdx.x, lane = tid & 31, wid = tid >> 5;
    int i = blockIdx.x * 1024 + tid;
    int v = (i < N) ? g_cnt[i] : 0;
    int s = v;
#pragma unroll
    for (int o = 1; o < 32; o <<= 1) {
        int t = __shfl_up_sync(0xffffffffu, s, o);
        if (lane >= o) s += t;
    }
    __shared__ int ws[32];
    if (lane == 31) ws[wid] = s;
    __syncthreads();
    if (wid == 0) {
        int w = ws[lane];
#pragma unroll
        for (int o = 1; o < 32; o <<= 1) {
            int t = __shfl_up_sync(0xffffffffu, w, o);
            if (lane >= o) w += t;
        }
        ws[lane] = w;
    }
    __syncthreads();
    int warp_off = (wid == 0) ? 0 : ws[wid - 1];
    int excl = g_bsumx[blockIdx.x] + warp_off + s - v;
    if (i < N) { g_off[i] = excl; g_cur[i] = excl; }
}

// ============ K5: CSR placement ============
__global__ __launch_bounds__(256) void place_kernel(const int* __restrict__ ei, int E) {
    int e = blockIdx.x * 256 + threadIdx.x;
    if (e >= E) return;
    int src = __ldg(&ei[e]);
    int dst = __ldg(&ei[(size_t)E + e]);
    int slot = atomicAdd(&g_cur[dst], 1);
    g_srcs[slot] = src;
}

// ============ K6: gather + mean + project (warp per node, unroll-4) ============
__global__ __launch_bounds__(256) void gather_kernel(float* __restrict__ out, int N) {
    int gw = (blockIdx.x * 256 + threadIdx.x) >> 5;
    int lane = threadIdx.x & 31;
    if (gw >= N) return;
    int beg = g_off[gw], end = g_off[gw + 1];
    const float2* hb = (const float2*)g_hbuf;
    float ax = 0.0f, ay = 0.0f;
    int j = beg;
    for (; j + 3 < end; j += 4) {
        int s0 = g_srcs[j];
        int s1 = g_srcs[j + 1];
        int s2 = g_srcs[j + 2];
        int s3 = g_srcs[j + 3];
        float2 a = hb[(size_t)s0 * 32 + lane];
        float2 b = hb[(size_t)s1 * 32 + lane];
        float2 c = hb[(size_t)s2 * 32 + lane];
        float2 d = hb[(size_t)s3 * 32 + lane];
        ax += (a.x + b.x) + (c.x + d.x);
        ay += (a.y + b.y) + (c.y + d.y);
    }
    for (; j < end; j++) {
        int s0 = g_srcs[j];
        float2 a = hb[(size_t)s0 * 32 + lane];
        ax += a.x;
        ay += a.y;
    }
    float dg = (float)(end - beg);
    float inv = 1.0f / fmaxf(dg, 1.0f);
    ax *= inv; ay *= inv;
    float n2 = ax * ax + ay * ay;
#pragma unroll
    for (int o = 16; o; o >>= 1) n2 += __shfl_xor_sync(0xffffffffu, n2, o);
    float nn = fmaxf(sqrtf(n2), EPSF);
    float sc = (nn > MAX_NORM) ? (MAX_NORM / nn) : 1.0f;
    ((float2*)out)[(size_t)gw * 32 + lane] = make_float2(ax * sc, ay * sc);
}

// ---------------- launch ----------------
extern "C" void kernel_launch(void* const* d_in, const int* in_sizes, int n_in,
                              void* d_out, int out_size) {
    const float* x      = (const float*)d_in[0];
    const float* weight = (const float*)d_in[1];
    const float* bias   = (const float*)d_in[2];
    const int*   ei     = (const int*)d_in[3];   // edge_index stored as int32
    float* out = (float*)d_out;

    int N = in_sizes[0] / D;
    int E = in_sizes[3] / 2;

    int zblocks = (N + 255) / 256;
    int tblocks = (N + 7) / 8;
    int cblocks = (E + 255) / 256;
    int nchunk  = (N + 1023) / 1024;

    zero_prep_kernel<<<zblocks + 1, 256>>>(weight, bias, N, zblocks);
    transform_count_kernel<<<tblocks + cblocks, 256>>>(x, ei, N, E, tblocks);
    scan_reduce_kernel<<<nchunk, 1024>>>(N);
    scan_tops_kernel<<<1, 1024>>>(nchunk, N);
    scan_write_kernel<<<nchunk, 1024>>>(N);
    place_kernel<<<cblocks, 256>>>(ei, E);
    gather_kernel<<<(N + 7) / 8, 256>>>(out, N);
}

// round 5
// speedup vs baseline: 1.4522x; 1.0317x over previous
#include <cuda_runtime.h>
#include <cuda_bf16.h>
#include <math.h>

#define EPSF 1e-7f
#define MAX_NORM (1.0f - 1e-5f)
#define MAXN 131072
#define MAXE 2097152
#define D 64

// ---------------- device scratch (no allocations allowed) ----------------
__device__ __align__(16) float g_wh[D * D];               // expmap0(weight)
__device__ __align__(16) float g_bh[D];                   // expmap0(bias)
__device__ float g_bh2;                                   // ||b_h||^2
__device__ __align__(16) float g_hbuf[(size_t)MAXN * D];  // transformed node features
__device__ int g_cnt[MAXN];                               // in-degree counts
__device__ int g_off[MAXN + 1];                           // CSR offsets
__device__ int g_cur[MAXN];                               // placement cursors
__device__ int g_srcs[MAXE];                              // CSR src list (grouped by dst)
__device__ volatile long long g_state[1024];              // lookback: (value<<32)|flag

// ============ K0: zero counters + lookback state + parameter transform ============
__global__ __launch_bounds__(256) void zero_prep_kernel(const float* __restrict__ weight,
                                                        const float* __restrict__ bias,
                                                        int N, int zblocks) {
    int b = blockIdx.x;
    if (b < zblocks) {
        int i = b * 256 + threadIdx.x;
        if (i < N) g_cnt[i] = 0;
        if (b == 0) {
            for (int k = threadIdx.x; k < 1024; k += 256) g_state[k] = 0;
        }
        return;
    }
    // prep block: 64 active threads
    int t = threadIdx.x;
    __shared__ float sh[D];
    if (t < D) {
        float row[D];
        float n2 = 0.0f;
#pragma unroll
        for (int j = 0; j < D; j++) {
            float v = weight[t * D + j];
            row[j] = v;
            n2 += v * v;
        }
        float n = fmaxf(sqrtf(n2), EPSF);
        float s = tanhf(n) / n;
#pragma unroll
        for (int j = 0; j < D; j++) g_wh[t * D + j] = s * row[j];
        float bb = bias[t];
        sh[t] = bb * bb;
    }
    __syncthreads();
    if (t == 0) {
        float s2 = 0.0f;
#pragma unroll
        for (int i = 0; i < D; i++) s2 += sh[i];
        sh[0] = s2;
    }
    __syncthreads();
    if (t < D) {
        float bn2 = sh[0];
        float bn = fmaxf(sqrtf(bn2), EPSF);
        float bs = tanhf(bn) / bn;
        g_bh[t] = bs * bias[t];
        if (t == 0) g_bh2 = bs * bs * bn2;
    }
}

// ============ K1: node transform + degree count (fused, role by blockIdx) ============
__global__ __launch_bounds__(256) void transform_count_kernel(const float* __restrict__ x,
                                                              const int* __restrict__ ei,
                                                              int N, int E, int tblocks) {
    int b = blockIdx.x;
    if (b >= tblocks) {
        // ---- count role ----
        int e = (b - tblocks) * 256 + threadIdx.x;
        if (e < E) {
            int dst = __ldg(&ei[(size_t)E + e]);
            atomicAdd(&g_cnt[dst], 1);
        }
        return;
    }
    // ---- transform role: warp per node ----
    __shared__ float2 Ws[D * 32];
    __shared__ float Bs[D];
    __shared__ float b2s;
    int tid = threadIdx.x;
    const float2* whv = (const float2*)g_wh;
    for (int i = tid; i < D * 32; i += 256) Ws[i] = whv[i];
    if (tid < D) Bs[tid] = g_bh[tid];
    if (tid == 0) b2s = g_bh2;
    __syncthreads();

    int warp = tid >> 5, lane = tid & 31;
    int node = b * 8 + warp;
    if (node >= N) return;

    float2 v = ((const float2*)x)[(size_t)node * 32 + lane];
    float xn2 = v.x * v.x + v.y * v.y;
#pragma unroll
    for (int o = 16; o; o >>= 1) xn2 += __shfl_xor_sync(0xffffffffu, xn2, o);
    float xn = fmaxf(sqrtf(xn2), EPSF);

    float m0 = 0.0f, m1 = 0.0f;
#pragma unroll
    for (int i = 0; i < D; i++) {
        float sel = (i & 1) ? v.y : v.x;
        float xi = __shfl_sync(0xffffffffu, sel, i >> 1);
        float2 w = Ws[i * 32 + lane];
        m0 = fmaf(xi, w.x, m0);
        m1 = fmaf(xi, w.y, m1);
    }
    float mn2 = m0 * m0 + m1 * m1;
#pragma unroll
    for (int o = 16; o; o >>= 1) mn2 += __shfl_xor_sync(0xffffffffu, mn2, o);
    float Mxn = fmaxf(sqrtf(mn2), EPSF);

    float xc = fminf(xn, 1.0f - 1e-7f);
    float art = 0.5f * log1pf(2.0f * xc / (1.0f - xc));
    float sc = tanhf(Mxn / xn * art) / Mxn;
    float h0 = sc * m0, h1 = sc * m1;

    float2 bb = ((const float2*)Bs)[lane];
    float xy = h0 * bb.x + h1 * bb.y;
    float xx = h0 * h0 + h1 * h1;
#pragma unroll
    for (int o = 16; o; o >>= 1) {
        xy += __shfl_xor_sync(0xffffffffu, xy, o);
        xx += __shfl_xor_sync(0xffffffffu, xx, o);
    }
    float y2 = b2s;
    float ca = 1.0f + 2.0f * xy + y2;
    float cb = 1.0f - xx;
    float den = fmaxf(1.0f + 2.0f * xy + xx * y2, EPSF);
    float inv = 1.0f / den;
    ((float2*)g_hbuf)[(size_t)node * 32 + lane] =
        make_float2((ca * h0 + cb * bb.x) * inv, (ca * h1 + cb * bb.y) * inv);
}

// ============ K2: single-pass decoupled-lookback exclusive scan ============
// flag: 1 = partial published, 2 = inclusive prefix published
__global__ __launch_bounds__(1024) void scan_lookback_kernel(int N, int nchunk) {
    int tid = threadIdx.x, lane = tid & 31, wid = tid >> 5;
    int bid = blockIdx.x;
    int i = bid * 1024 + tid;
    int v = (i < N) ? g_cnt[i] : 0;
    // block-local inclusive scan
    int s = v;
#pragma unroll
    for (int o = 1; o < 32; o <<= 1) {
        int t = __shfl_up_sync(0xffffffffu, s, o);
        if (lane >= o) s += t;
    }
    __shared__ int ws[32];
    __shared__ int base_s;
    if (lane == 31) ws[wid] = s;
    __syncthreads();
    if (wid == 0) {
        int w = ws[lane];
#pragma unroll
        for (int o = 1; o < 32; o <<= 1) {
            int t = __shfl_up_sync(0xffffffffu, w, o);
            if (lane >= o) w += t;
        }
        ws[lane] = w;
    }
    __syncthreads();
    int warp_off = (wid == 0) ? 0 : ws[wid - 1];
    int block_total = ws[31];

    // publish + lookback (thread 0)
    if (tid == 0) {
        if (bid == 0) {
            __threadfence();
            g_state[0] = ((long long)block_total << 32) | 2ll;
            base_s = 0;
        } else {
            // publish partial
            __threadfence();
            g_state[bid] = ((long long)block_total << 32) | 1ll;
            // lookback
            int base = 0;
            int k = bid - 1;
            while (k >= 0) {
                long long st = g_state[k];
                int flag = (int)(st & 3ll);
                if (flag == 0) continue;           // spin
                base += (int)(st >> 32);
                if (flag == 2) break;
                k--;
            }
            // publish inclusive prefix
            __threadfence();
            g_state[bid] = ((long long)(base + block_total) << 32) | 2ll;
            base_s = base;
        }
    }
    __syncthreads();
    int base = base_s;
    int excl = base + warp_off + s - v;
    if (i < N) { g_off[i] = excl; g_cur[i] = excl; }
    if (bid == nchunk - 1 && tid == 1023) g_off[N] = base + block_total;
}

// ============ K3: CSR placement (2 edges per thread) ============
__global__ __launch_bounds__(256) void place_kernel(const int* __restrict__ ei, int E) {
    int t = blockIdx.x * 256 + threadIdx.x;
    int e = t * 2;
    if (e >= E) return;
    if (e + 1 < E) {
        int2 sp = *(const int2*)&ei[e];
        int2 dp = *(const int2*)&ei[(size_t)E + e];
        int slot0 = atomicAdd(&g_cur[dp.x], 1);
        int slot1 = atomicAdd(&g_cur[dp.y], 1);
        g_srcs[slot0] = sp.x;
        g_srcs[slot1] = sp.y;
    } else {
        int src = __ldg(&ei[e]);
        int dst = __ldg(&ei[(size_t)E + e]);
        int slot = atomicAdd(&g_cur[dst], 1);
        g_srcs[slot] = src;
    }
}

// ============ K4: gather + mean + project (warp/node, float4, 2 edges per load) ============
__global__ __launch_bounds__(256) void gather_kernel(float* __restrict__ out, int N) {
    int gw = (blockIdx.x * 256 + threadIdx.x) >> 5;
    int lane = threadIdx.x & 31;
    if (gw >= N) return;
    int beg = g_off[gw], end = g_off[gw + 1];
    int h = lane >> 4;       // half-warp id: handles edges beg+h, beg+h+2, ...
    int c = lane & 15;       // float4 column within row
    const float4* hb = (const float4*)g_hbuf;
    float4 acc = make_float4(0.f, 0.f, 0.f, 0.f);
    int j = beg + h;
    for (; j + 6 < end; j += 8) {
        int s0 = g_srcs[j];
        int s1 = g_srcs[j + 2];
        int s2 = g_srcs[j + 4];
        int s3 = g_srcs[j + 6];
        float4 a = hb[(size_t)s0 * 16 + c];
        float4 b = hb[(size_t)s1 * 16 + c];
        float4 cc = hb[(size_t)s2 * 16 + c];
        float4 d = hb[(size_t)s3 * 16 + c];
        acc.x += (a.x + b.x) + (cc.x + d.x);
        acc.y += (a.y + b.y) + (cc.y + d.y);
        acc.z += (a.z + b.z) + (cc.z + d.z);
        acc.w += (a.w + b.w) + (cc.w + d.w);
    }
    for (; j < end; j += 2) {
        int s0 = g_srcs[j];
        float4 a = hb[(size_t)s0 * 16 + c];
        acc.x += a.x; acc.y += a.y; acc.z += a.z; acc.w += a.w;
    }
    // combine the two halves (lane l and l^16 hold same columns, different edges)
    acc.x += __shfl_xor_sync(0xffffffffu, acc.x, 16);
    acc.y += __shfl_xor_sync(0xffffffffu, acc.y, 16);
    acc.z += __shfl_xor_sync(0xffffffffu, acc.z, 16);
    acc.w += __shfl_xor_sync(0xffffffffu, acc.w, 16);

    float dg = (float)(end - beg);
    float inv = 1.0f / fmaxf(dg, 1.0f);
    acc.x *= inv; acc.y *= inv; acc.z *= inv; acc.w *= inv;

    float n2 = acc.x * acc.x + acc.y * acc.y + acc.z * acc.z + acc.w * acc.w;
#pragma unroll
    for (int o = 8; o; o >>= 1) n2 += __shfl_xor_sync(0xffffffffu, n2, o);
    float nn = fmaxf(sqrtf(n2), EPSF);
    float sc = (nn > MAX_NORM) ? (MAX_NORM / nn) : 1.0f;
    if (h == 0) {
        ((float4*)out)[(size_t)gw * 16 + c] =
            make_float4(acc.x * sc, acc.y * sc, acc.z * sc, acc.w * sc);
    }
}

// ---------------- launch ----------------
extern "C" void kernel_launch(void* const* d_in, const int* in_sizes, int n_in,
                              void* d_out, int out_size) {
    const float* x      = (const float*)d_in[0];
    const float* weight = (const float*)d_in[1];
    const float* bias   = (const float*)d_in[2];
    const int*   ei     = (const int*)d_in[3];   // edge_index stored as int32
    float* out = (float*)d_out;

    int N = in_sizes[0] / D;
    int E = in_sizes[3] / 2;

    int zblocks = (N + 255) / 256;
    int tblocks = (N + 7) / 8;
    int cblocks = (E + 255) / 256;
    int nchunk  = (N + 1023) / 1024;
    int pblocks = ((E + 1) / 2 + 255) / 256;

    zero_prep_kernel<<<zblocks + 1, 256>>>(weight, bias, N, zblocks);
    transform_count_kernel<<<tblocks + cblocks, 256>>>(x, ei, N, E, tblocks);
    scan_lookback_kernel<<<nchunk, 1024>>>(N, nchunk);
    place_kernel<<<pblocks, 256>>>(ei, E);
    gather_kernel<<<(N + 7) / 8, 256>>>(out, N);
}